// round 8
// baseline (speedup 1.0000x reference)
#include <cuda_runtime.h>

// MPULoss_INDEX: N x 128 softmax PU loss -> 3 scalars, single fused kernel.
// OCTET-per-row layout: 8 lanes/row, 16 classes/lane, 4 rows per warp-step.
// f32x2 packed math for the fma-pipe stream; arithmetic masking (no FSEL/bit
// extraction). log2-domain float accumulation; FP64 only in finalize.
// Inputs: outputs f32[N,128], labels i32[N] (==128 -> U), prior f32[128],
// indexlist i32[L=32]. Output f32[3] = (cross, PULoss, cross), PUW=1.

#define KC 128
#define WARPS_PER_BLOCK 4
#define THREADS (WARPS_PER_BLOCK * 32)
#define NBLOCKS 1184
#define LN2F   0.6931471805599453f
#define LOG2EF 1.4426950408889634f
#define FULLM 0xffffffffu

typedef unsigned long long ull;

__device__ double g_sIn, g_sOut, g_sPu2, g_sCe;   // zero-init; reset by last block
__device__ unsigned long long g_cntP;
__device__ unsigned int g_ticket;

// ---- f32x2 helpers (PTX-only; ptxas won't auto-fuse) ----
__device__ __forceinline__ ull pack2(float lo, float hi) {
    ull r; asm("mov.b64 %0, {%1, %2};" : "=l"(r) : "f"(lo), "f"(hi)); return r;
}
__device__ __forceinline__ void unpack2(ull v, float& lo, float& hi) {
    asm("mov.b64 {%0, %1}, %2;" : "=f"(lo), "=f"(hi) : "l"(v));
}
__device__ __forceinline__ ull fma2(ull a, ull b, ull c) {
    ull r; asm("fma.rn.f32x2 %0, %1, %2, %3;" : "=l"(r) : "l"(a), "l"(b), "l"(c)); return r;
}
__device__ __forceinline__ ull mul2(ull a, ull b) {
    ull r; asm("mul.rn.f32x2 %0, %1, %2;" : "=l"(r) : "l"(a), "l"(b)); return r;
}
__device__ __forceinline__ ull add2(ull a, ull b) {
    ull r; asm("add.rn.f32x2 %0, %1, %2;" : "=l"(r) : "l"(a), "l"(b)); return r;
}

__device__ __forceinline__ float pick4(float a, float b, float c, float d, int j) {
    float r = a;
    if (j == 1) r = b;
    if (j == 2) r = c;
    if (j == 3) r = d;
    return r;
}

// One 4-row group. Lane = oct*8 + sub: row = rbase+oct, classes [sub*16,+16).
__device__ __forceinline__ void process_group(
    const float4& A, const float4& B, const float4& C, const float4& D,
    int lb, bool act, const ull* mIn2, int lane, int sub,
    const float* __restrict__ prior,
    float& aIn, float& aOut, float& aPu2, float& aCe, unsigned& cP)
{
    const ull L2E2 = pack2(LOG2EF, LOG2EF);

    // pack logits into 8 f32x2, scale by log2(e), exp2 per component
    ull x2[8];
    x2[0] = pack2(A.x, A.y); x2[1] = pack2(A.z, A.w);
    x2[2] = pack2(B.x, B.y); x2[3] = pack2(B.z, B.w);
    x2[4] = pack2(C.x, C.y); x2[5] = pack2(C.z, C.w);
    x2[6] = pack2(D.x, D.y); x2[7] = pack2(D.z, D.w);

    float e[16];
    ull e2[8];
    #pragma unroll
    for (int k = 0; k < 8; k++) {
        ull s = mul2(x2[k], L2E2);
        float lo, hi; unpack2(s, lo, hi);
        float el = exp2f(lo), eh = exp2f(hi);
        e[2*k] = el; e[2*k+1] = eh;
        e2[k] = pack2(el, eh);
    }

    // z = sum of all 128 e across octet: packed tree then 3-step octet shfl
    ull zs = add2(add2(add2(e2[0], e2[1]), add2(e2[2], e2[3])),
                  add2(add2(e2[4], e2[5]), add2(e2[6], e2[7])));
    float zlo, zhi; unpack2(zs, zlo, zhi);
    float z = zlo + zhi;
    z += __shfl_xor_sync(FULLM, z, 1);
    z += __shfl_xor_sync(FULLM, z, 2);
    z += __shfl_xor_sync(FULLM, z, 4);
    const float rz = __fdividef(1.0f, z);

    const bool isP = (lb < KC);
    const float isPf = isP ? 1.0f : 0.0f;

    // m = mIn*(1-2*isP) + isP  (exact for m in {0,1})
    // f = m*(t-1) + 1,  t-1 = e*(-rz) + 0.01
    const ull k2   = pack2(1.0f - 2.0f * isPf, 1.0f - 2.0f * isPf);
    const ull i2   = pack2(isPf, isPf);
    const ull nrz2 = pack2(-rz, -rz);
    const ull eps2 = pack2(0.01f, 0.01f);
    const ull one2 = pack2(1.0f, 1.0f);

    ull p2 = one2;
    #pragma unroll
    for (int k = 0; k < 8; k++) {
        ull tm1 = fma2(e2[k], nrz2, eps2);
        ull m2  = fma2(mIn2[k], k2, i2);
        ull f2  = fma2(m2, tm1, one2);
        p2 = mul2(p2, f2);
    }
    float plo, phi; unpack2(p2, plo, phi);
    float p = plo * phi;
    p *= __shfl_xor_sync(FULLM, p, 1);
    p *= __shfl_xor_sync(FULLM, p, 2);
    p *= __shfl_xor_sync(FULLM, p, 4);   // selected product for whole row

    // capture e[label]: within-lane pick from 16, then one shfl from owner
    const int j0 = lb & 3, j1 = (lb >> 2) & 3;
    float c0 = pick4(e[0],  e[1],  e[2],  e[3],  j0);
    float c1 = pick4(e[4],  e[5],  e[6],  e[7],  j0);
    float c2 = pick4(e[8],  e[9],  e[10], e[11], j0);
    float c3 = pick4(e[12], e[13], e[14], e[15], j0);
    float cand = pick4(c0, c1, c2, c3, j1);
    float elb = __shfl_sync(FULLM, cand, (lane & 0x18) | ((lb >> 4) & 7));

    if (act && sub == 0) {                 // octet leader: scalar tail
        float s = __log2f(p);              // sum log2(t) over selected classes
        if (isP) {
            aOut += s; cP++;
            float pj = __ldg(prior + lb);
            float tl = fmaf(elb, -rz, 1.01f);
            aPu2 += __log2f(tl) * pj;      // final: * -ln2
            aCe  += LN2F * (__log2f(z) - __log2f(elb));  // ln z - v_label
        } else {
            aIn += s;                      // final: * -ln2
        }
    }
}

__global__ void __launch_bounds__(THREADS)
mpul_fused(const float* __restrict__ outputs,
           const int*   __restrict__ labels,
           const float* __restrict__ prior,
           const int*   __restrict__ indexlist,
           float* __restrict__ out,
           int N, int rowsPerWarp, int L) {
    const int lane   = threadIdx.x & 31;
    const int sub    = lane & 7;
    const int oct    = lane >> 3;
    const int wInBlk = threadIdx.x >> 5;
    const int warp   = blockIdx.x * WARPS_PER_BLOCK + wInBlk;

    // Per-lane membership of classes [sub*16, sub*16+16) as 8 packed 0/1 pairs
    int il = (lane < L) ? indexlist[lane] : -1;
    unsigned mymask = 0;
    #pragma unroll
    for (int j = 0; j < 32; j++) {
        int cc = __shfl_sync(FULLM, il, j);
        if (cc >= 0 && (cc >> 4) == sub) mymask |= 1u << (cc & 15);
    }
    ull mIn2[8];
    #pragma unroll
    for (int k = 0; k < 8; k++) {
        float lo = (mymask >> (2*k))     & 1u ? 1.0f : 0.0f;
        float hi = (mymask >> (2*k + 1)) & 1u ? 1.0f : 0.0f;
        mIn2[k] = pack2(lo, hi);
    }

    float aIn = 0.f, aOut = 0.f, aPu2 = 0.f, aCe = 0.f;
    unsigned cP = 0;

    const float4* __restrict__ out4 = (const float4*)outputs;
    const int start = warp * rowsPerWarp;
    const int end   = min(start + rowsPerWarp, N);

    int r = start;
    float4 v0, v1, v2, v3; int lb;
    bool have = (r + 4 <= end);
    if (have) {
        const float4* bp = out4 + (size_t)(r + oct) * 32 + sub * 4;
        v0 = bp[0]; v1 = bp[1]; v2 = bp[2]; v3 = bp[3];
        lb = labels[r + oct];
    }

    while (have) {
        const int rn = r + 4;
        const bool haveN = (rn + 4 <= end);
        float4 w0, w1, w2, w3; int lbn;
        if (haveN) {                          // prefetch next group
            const float4* bp = out4 + (size_t)(rn + oct) * 32 + sub * 4;
            w0 = bp[0]; w1 = bp[1]; w2 = bp[2]; w3 = bp[3];
            lbn = labels[rn + oct];
        }

        process_group(v0, v1, v2, v3, lb, true, mIn2, lane, sub,
                      prior, aIn, aOut, aPu2, aCe, cP);

        v0 = w0; v1 = w1; v2 = w2; v3 = w3; lb = lbn;
        r = rn; have = haveN;
    }

    if (r < end) {                            // tail: 0..3 rows
        const int rem = end - r;
        const bool act = (oct < rem);
        const int rr = r + (act ? oct : 0);
        const float4* bp = out4 + (size_t)rr * 32 + sub * 4;
        float4 t0 = bp[0], t1 = bp[1], t2 = bp[2], t3 = bp[3];
        int tlb = labels[rr];
        process_group(t0, t1, t2, t3, tlb, act, mIn2, lane, sub,
                      prior, aIn, aOut, aPu2, aCe, cP);
    }

    // accumulators live on octet-leader lanes (0,8,16,24): 2-step reduce
    #pragma unroll
    for (int o = 8; o < 32; o <<= 1) {
        aIn  += __shfl_xor_sync(FULLM, aIn,  o);
        aOut += __shfl_xor_sync(FULLM, aOut, o);
        aPu2 += __shfl_xor_sync(FULLM, aPu2, o);
        aCe  += __shfl_xor_sync(FULLM, aCe,  o);
        cP   += __shfl_xor_sync(FULLM, cP,   o);
    }

    __shared__ double sh[WARPS_PER_BLOCK][4];
    __shared__ unsigned shc[WARPS_PER_BLOCK];
    if (lane == 0) {                          // one F64 convert per warp
        sh[wInBlk][0] = (double)aIn;
        sh[wInBlk][1] = (double)aOut;
        sh[wInBlk][2] = (double)aPu2;
        sh[wInBlk][3] = (double)aCe;
        shc[wInBlk] = cP;
    }
    __syncthreads();

    if (threadIdx.x == 0) {
        double tIn = 0, tOut = 0, tPu2 = 0, tCe = 0;
        unsigned long long tc = 0;
        #pragma unroll
        for (int i = 0; i < WARPS_PER_BLOCK; i++) {
            tIn += sh[i][0]; tOut += sh[i][1]; tPu2 += sh[i][2]; tCe += sh[i][3];
            tc += shc[i];
        }
        atomicAdd(&g_sIn,  tIn);
        atomicAdd(&g_sOut, tOut);
        atomicAdd(&g_sPu2, tPu2);
        atomicAdd(&g_sCe,  tCe);
        atomicAdd(&g_cntP, tc);

        __threadfence();
        unsigned ticket = atomicAdd(&g_ticket, 1u);
        if (ticket == gridDim.x - 1u) {
            // ---- last block: finalize (scale log2 sums by -ln2 here) ----
            double sIn  = -(double)LN2F * __longlong_as_double(
                (long long)atomicAdd((unsigned long long*)&g_sIn, 0ull));
            double sOut = -(double)LN2F * __longlong_as_double(
                (long long)atomicAdd((unsigned long long*)&g_sOut, 0ull));
            double sPu2 = -(double)LN2F * __longlong_as_double(
                (long long)atomicAdd((unsigned long long*)&g_sPu2, 0ull));
            double sCe  = __longlong_as_double(
                (long long)atomicAdd((unsigned long long*)&g_sCe, 0ull));
            unsigned long long cnt = atomicAdd(&g_cntP, 0ull);

            double nP = (cnt > 0ull) ? (double)cnt : 1.0;
            long long nUll = (long long)N - (long long)cnt;
            double nU = (nUll > 0) ? (double)nUll : 1.0;

            double pu3 = sIn / nU / (double)L;
            double pu1 = sOut * (double)prior[indexlist[0]] / nP / (double)(KC - L);
            double pu2 = sPu2 / nP;
            double cross = sCe / nP;
            double puloss = pu3 + pu1 - pu2;      // PUW = 1

            out[0] = (float)cross;
            out[1] = (float)puloss;
            out[2] = (float)cross;

            // reset for the next graph replay (deterministic)
            atomicExch((unsigned long long*)&g_sIn,  0ull);
            atomicExch((unsigned long long*)&g_sOut, 0ull);
            atomicExch((unsigned long long*)&g_sPu2, 0ull);
            atomicExch((unsigned long long*)&g_sCe,  0ull);
            atomicExch(&g_cntP, 0ull);
            atomicExch(&g_ticket, 0u);
        }
    }
}

extern "C" void kernel_launch(void* const* d_in, const int* in_sizes, int n_in,
                              void* d_out, int out_size) {
    const float* outputs   = (const float*)d_in[0];
    const int*   labels    = (const int*)d_in[1];
    const float* prior     = (const float*)d_in[2];
    const int*   indexlist = (const int*)d_in[3];
    const int N = in_sizes[1];
    const int L = in_sizes[3];

    const int nwarps = NBLOCKS * WARPS_PER_BLOCK;   // 4736
    int rowsPerWarp = (N + nwarps - 1) / nwarps;
    rowsPerWarp = (rowsPerWarp + 3) & ~3;           // multiple of 4

    mpul_fused<<<NBLOCKS, THREADS>>>(outputs, labels, prior, indexlist,
                                     (float*)d_out, N, rowsPerWarp, L);
}